// round 4
// baseline (speedup 1.0000x reference)
#include <cuda_runtime.h>

#define CH   4194304      // 256*256*64
#define SXY  16384        // 256*64 (x stride)
#define EPSF 1e-10f

__device__ double g_acc[3];   // [0]=loss_b sum, [1]=parallel sum, [2]=div sum

__global__ void k_zero() {
    if (threadIdx.x < 3) g_acc[threadIdx.x] = 0.0;
}

__global__ void k_final(float* out) {
    const double N1 = 8388608.0;   // 2*256*256*64
    const double N2 = 8193150.0;   // 2*255*255*63
    double lb = g_acc[0] / N1;
    double lp = g_acc[1] / N1;
    double ld = g_acc[2] / N2;
    double dx2 = 0.1 * 0.1;
    out[0] = (float)(1000.0 * lb + 1000.0 * lp);
    out[1] = (float)(100.0 * ld / dx2 / dx2);
}

// Thread layout: tx 0..31 -> k0 = 2*tx (one warp = one full contiguous k-row of
// one (x,y)); ty 0..7 -> y within group. Grid: b(2) * x(256) * ygroup(32).
__global__ __launch_bounds__(256)
void k_main(const float* __restrict__ O, const float* __restrict__ T) {
    const int tx = threadIdx.x;          // 0..31
    const int ty = threadIdx.y;          // 0..7
    const int bid = blockIdx.x;          // 16384 blocks
    const int y  = ((bid & 31) << 3) + ty;
    const int x  = (bid >> 5) & 255;
    const int b  = bid >> 13;
    const int k0 = tx << 1;
    const int sp = (x * 256 + y) * 64 + k0;
    const int ob = b * 3 * CH;           // outputs batch base
    const int tb = b * 4 * CH;           // targets batch base

    const float2* O2 = (const float2*)O;
    const float2* T2 = (const float2*)T;

    // ---- pointwise channel loads (also the (0,0,k0..k0+1) stencil corners) ----
    float2 pbx = O2[(ob           + sp) >> 1];
    float2 pby = O2[(ob + CH      + sp) >> 1];
    float2 pbz = O2[(ob + 2 * CH  + sp) >> 1];
    float2 qbx = T2[(tb           + sp) >> 1];
    float2 qby = T2[(tb + CH      + sp) >> 1];
    float2 qbz = T2[(tb + 2 * CH  + sp) >> 1];

    float accb = 0.f, accp = 0.f, accd = 0.f;

#define PW(px, py, pz, qx, qy, qz) {                                   \
    float qx2 = (qx)*(qx), qy2 = (qy)*(qy), qz2 = (qz)*(qz);           \
    float v1 = (px)*(px) + (py)*(py) - qx2 - qy2;                      \
    accb += __fdividef(v1 * v1, qx2 + qy2 + EPSF);                     \
    float dz = (pz) - (qz); float dz2 = dz * dz;                       \
    accb += __fdividef(dz2 * dz2, qz2 + EPSF);                         \
    float cr = (px)*(qy) - (py)*(qx);                                  \
    accp += __fdividef(cr * cr, qx2 + qy2 + qz2 + EPSF); }

    PW(pbx.x, pby.x, pbz.x, qbx.x, qby.x, qbz.x);
    PW(pbx.y, pby.y, pbz.y, qbx.y, qby.y, qbz.y);
#undef PW

    // ---- divergence stencil over cells (x<255, y<255, k<63) ----
    const bool live = (x < 255) && (y < 255);

    float2 fx10, fx01, fx11, fy10, fy01, fy11, fz10, fz01, fz11;
    float2 fw00, fw10, fw01, fw11;
    if (live) {
        const int s10 = sp + SXY;      // x+1
        const int s01 = sp + 64;       // y+1
        const int s11 = s10 + 64;      // x+1, y+1
        const int cz  = tb + 3 * CH;   // targets channel 3 (z)
        fx10 = O2[(ob          + s10) >> 1];
        fx01 = O2[(ob          + s01) >> 1];
        fx11 = O2[(ob          + s11) >> 1];
        fy10 = O2[(ob + CH     + s10) >> 1];
        fy01 = O2[(ob + CH     + s01) >> 1];
        fy11 = O2[(ob + CH     + s11) >> 1];
        fz10 = O2[(ob + 2*CH   + s10) >> 1];
        fz01 = O2[(ob + 2*CH   + s01) >> 1];
        fz11 = O2[(ob + 2*CH   + s11) >> 1];
        fw00 = T2[(cz          + sp ) >> 1];
        fw10 = T2[(cz          + s10) >> 1];
        fw01 = T2[(cz          + s01) >> 1];
        fw11 = T2[(cz          + s11) >> 1];
    } else {
        fx10 = fx01 = fx11 = fy10 = fy01 = fy11 = fz10 = fz01 = fz11 =
        fw00 = fw10 = fw01 = fw11 = make_float2(0.f, 0.f);
    }

    // k0+2 tail from lane tx+1's .x (full-warp shfl; lane 31 result unused
    // since its second cell k0+1 == 63 is out of range anyway).
    const unsigned FULL = 0xffffffffu;
    float tBX00 = __shfl_down_sync(FULL, pbx.x,  1);
    float tBX10 = __shfl_down_sync(FULL, fx10.x, 1);
    float tBX01 = __shfl_down_sync(FULL, fx01.x, 1);
    float tBX11 = __shfl_down_sync(FULL, fx11.x, 1);
    float tBY00 = __shfl_down_sync(FULL, pby.x,  1);
    float tBY10 = __shfl_down_sync(FULL, fy10.x, 1);
    float tBY01 = __shfl_down_sync(FULL, fy01.x, 1);
    float tBY11 = __shfl_down_sync(FULL, fy11.x, 1);
    float tBZ00 = __shfl_down_sync(FULL, pbz.x,  1);
    float tBZ10 = __shfl_down_sync(FULL, fz10.x, 1);
    float tBZ01 = __shfl_down_sync(FULL, fz01.x, 1);
    float tBZ11 = __shfl_down_sync(FULL, fz11.x, 1);
    float tZZ00 = __shfl_down_sync(FULL, fw00.x, 1);
    float tZZ10 = __shfl_down_sync(FULL, fw10.x, 1);
    float tZZ01 = __shfl_down_sync(FULL, fw01.x, 1);
    float tZZ11 = __shfl_down_sync(FULL, fw11.x, 1);

    if (live) {
        float BX00[3] = {pbx.x, pbx.y, tBX00};
        float BX10[3] = {fx10.x, fx10.y, tBX10};
        float BX01[3] = {fx01.x, fx01.y, tBX01};
        float BX11[3] = {fx11.x, fx11.y, tBX11};
        float BY00[3] = {pby.x, pby.y, tBY00};
        float BY10[3] = {fy10.x, fy10.y, tBY10};
        float BY01[3] = {fy01.x, fy01.y, tBY01};
        float BY11[3] = {fy11.x, fy11.y, tBY11};
        float BZ00[3] = {pbz.x, pbz.y, tBZ00};
        float BZ10[3] = {fz10.x, fz10.y, tBZ10};
        float BZ01[3] = {fz01.x, fz01.y, tBZ01};
        float BZ11[3] = {fz11.x, fz11.y, tBZ11};
        float ZZ00[3] = {fw00.x, fw00.y, tZZ00};
        float ZZ10[3] = {fw10.x, fw10.y, tZZ10};
        float ZZ01[3] = {fw01.x, fw01.y, tZZ01};
        float ZZ11[3] = {fw11.x, fw11.y, tZZ11};

        const float DXf = 0.1f, DYf = 0.1f;
        const float SIXTH = 1.f / 6.f;

#pragma unroll
        for (int j = 0; j < 2; j++) {
            if (k0 + j < 63) {
                float bx000 = BX00[j], bx001 = BX00[j+1];
                float bx100 = BX10[j], bx101 = BX10[j+1];
                float bx010 = BX01[j], bx011 = BX01[j+1];
                float bx110 = BX11[j], bx111 = BX11[j+1];
                float by000 = BY00[j], by001 = BY00[j+1];
                float by100 = BY10[j], by101 = BY10[j+1];
                float by010 = BY01[j], by011 = BY01[j+1];
                float by110 = BY11[j], by111 = BY11[j+1];
                float bz000 = BZ00[j], bz001 = BZ00[j+1];
                float bz100 = BZ10[j], bz101 = BZ10[j+1];
                float bz010 = BZ01[j], bz011 = BZ01[j+1];
                float bz110 = BZ11[j], bz111 = BZ11[j+1];
                float z000  = ZZ00[j], z001  = ZZ00[j+1];
                float z100  = ZZ10[j], z101  = ZZ10[j+1];
                float z010  = ZZ01[j], z011  = ZZ01[j+1];
                float z110  = ZZ11[j], z111  = ZZ11[j+1];

                float num =
                    0.25f*(bx100+bx110+bx101+bx111) * DYf * 0.5f*(z101 - z100 + z111 - z110)
                  - 0.25f*(bx000+bx010+bx001+bx011) * DYf * 0.5f*(z001 - z000 + z011 - z010)
                  + 0.25f*(by010+by110+by011+by111) * DXf * 0.5f*(z011 - z010 + z111 - z110)
                  - 0.25f*(by000+by100+by001+by101) * DXf * 0.5f*(z001 - z000 + z101 - z100)
                  + 0.25f*(bz001+bz011+bz101+bz111) * DXf * DYf
                  - 0.25f*(bz000+bz010+bz100+bz110) * DXf * DYf
                  + (bx001+bx101+bx111) * DYf * (z001 - z101) * SIXTH
                  + (bx011+bx111+bx101) * DYf * (z011 - z111) * SIXTH
                  + (by101+by111+by011) * DXf * (z101 - z111) * SIXTH
                  + (by001+by011+by111) * DXf * (z001 - z011) * SIXTH
                  - (bx000+bx100+bx110) * DYf * (z000 - z100) * SIXTH
                  - (bx010+bx110+bx100) * DYf * (z010 - z110) * SIXTH
                  - (by100+by110+by010) * DXf * (z100 - z110) * SIXTH
                  - (by000+by010+by110) * DXf * (z000 - z010) * SIXTH;

                float bxc = 0.125f*(bx000+bx100+bx010+bx110+bx001+bx101+bx011+bx111);
                float byc = 0.125f*(by000+by100+by010+by110+by001+by101+by011+by111);
                float bzc = 0.125f*(bz000+bz100+bz010+bz110+bz001+bz101+bz011+bz111);
                float den = bxc*bxc + byc*byc + bzc*bzc + EPSF;
                accd += __fdividef(num * num, den);
            }
        }
    }

    // ---- reduction: warp shfl (double) -> smem -> 3 atomics per block ----
    double db = (double)accb, dp = (double)accp, dd = (double)accd;
#pragma unroll
    for (int o = 16; o > 0; o >>= 1) {
        db += __shfl_xor_sync(0xffffffffu, db, o);
        dp += __shfl_xor_sync(0xffffffffu, dp, o);
        dd += __shfl_xor_sync(0xffffffffu, dd, o);
    }
    __shared__ double sb[8], sp_[8], sd[8];
    if (tx == 0) {
        sb[ty] = db; sp_[ty] = dp; sd[ty] = dd;
    }
    __syncthreads();
    if (tx == 0 && ty == 0) {
        double a = 0.0, c = 0.0, d = 0.0;
#pragma unroll
        for (int w = 0; w < 8; w++) { a += sb[w]; c += sp_[w]; d += sd[w]; }
        atomicAdd(&g_acc[0], a);
        atomicAdd(&g_acc[1], c);
        atomicAdd(&g_acc[2], d);
    }
}

extern "C" void kernel_launch(void* const* d_in, const int* in_sizes, int n_in,
                              void* d_out, int out_size) {
    const float* O = (const float*)d_in[0];   // outputs (2,3,256,256,64)
    const float* T = (const float*)d_in[1];   // targets (2,4,256,256,64)
    k_zero<<<1, 32>>>();
    k_main<<<16384, dim3(32, 8)>>>(O, T);
    k_final<<<1, 1>>>((float*)d_out);
}

// round 6
// speedup vs baseline: 1.2679x; 1.2679x over previous
#include <cuda_runtime.h>

#define CH   4194304      // 256*256*64
#define SXY  16384        // 256*64 (x stride)
#define EPSF 1e-10f

__device__ double g_acc[3];        // [0]=loss_b, [1]=parallel, [2]=div
__device__ unsigned int g_done;    // zero-initialized

// Thread layout: tx 0..15 -> k0=4*tx, ty 0..7 -> y in group.
// Grid: 16384 = b(2) * x(256) * ygroup(32).
__global__ __launch_bounds__(128, 3)
void k_main(const float* __restrict__ O, const float* __restrict__ T,
            float* __restrict__ out, int nblocks) {
    const int tx = threadIdx.x;          // 0..15
    const int ty = threadIdx.y;          // 0..7
    const int bid = blockIdx.x;
    const int y  = ((bid & 31) << 3) + ty;
    const int x  = (bid >> 5) & 255;
    const int b  = bid >> 13;
    const int k0 = tx << 2;
    const int sp = (x * 256 + y) * 64 + k0;
    const int ob = b * 3 * CH;
    const int tb = b * 4 * CH;

    const float4* O4 = (const float4*)O;
    const float4* T4 = (const float4*)T;

    // ---- pointwise loads (double as (0,0) stencil corners) ----
    float4 pbx = O4[(ob           + sp) >> 2];
    float4 pby = O4[(ob + CH      + sp) >> 2];
    float4 pbz = O4[(ob + 2 * CH  + sp) >> 2];
    float4 qbx = T4[(tb           + sp) >> 2];
    float4 qby = T4[(tb + CH      + sp) >> 2];
    float4 qbz = T4[(tb + 2 * CH  + sp) >> 2];

    float accb = 0.f, accp = 0.f, accd = 0.f;

#define PW(px, py, pz, qx, qy, qz) {                                   \
    float qx2 = (qx)*(qx), qy2 = (qy)*(qy), qz2 = (qz)*(qz);           \
    float v1 = (px)*(px) + (py)*(py) - qx2 - qy2;                      \
    accb += __fdividef(v1 * v1, qx2 + qy2 + EPSF);                     \
    float dz = (pz) - (qz); float dz2 = dz * dz;                       \
    accb += __fdividef(dz2 * dz2, qz2 + EPSF);                         \
    float cr = (px)*(qy) - (py)*(qx);                                  \
    accp += __fdividef(cr * cr, qx2 + qy2 + qz2 + EPSF); }

    PW(pbx.x, pby.x, pbz.x, qbx.x, qby.x, qbz.x);
    PW(pbx.y, pby.y, pbz.y, qbx.y, qby.y, qbz.y);
    PW(pbx.z, pby.z, pbz.z, qbx.z, qby.z, qbz.z);
    PW(pbx.w, pby.w, pbz.w, qbx.w, qby.w, qbz.w);
#undef PW

    // ---- divergence stencil over cells (x<255, y<255, k<63) ----
    const bool live = (x < 255) && (y < 255);

    float4 fx10, fx01, fx11, fy10, fy01, fy11, fz10, fz01, fz11;
    float4 fw00, fw10, fw01, fw11;
    if (live) {
        const int s10 = sp + SXY;
        const int s01 = sp + 64;
        const int s11 = s10 + 64;
        const int cz  = tb + 3 * CH;
        fx10 = O4[(ob          + s10) >> 2];
        fx01 = O4[(ob          + s01) >> 2];
        fx11 = O4[(ob          + s11) >> 2];
        fy10 = O4[(ob + CH     + s10) >> 2];
        fy01 = O4[(ob + CH     + s01) >> 2];
        fy11 = O4[(ob + CH     + s11) >> 2];
        fz10 = O4[(ob + 2*CH   + s10) >> 2];
        fz01 = O4[(ob + 2*CH   + s01) >> 2];
        fz11 = O4[(ob + 2*CH   + s11) >> 2];
        fw00 = T4[(cz          + sp ) >> 2];
        fw10 = T4[(cz          + s10) >> 2];
        fw01 = T4[(cz          + s01) >> 2];
        fw11 = T4[(cz          + s11) >> 2];
    } else {
        fx10 = fx01 = fx11 = fy10 = fy01 = fy11 = fz10 = fz01 = fz11 =
        fw00 = fw10 = fw01 = fw11 = make_float4(0.f, 0.f, 0.f, 0.f);
    }

    // k0+4 tail from lane+1's .x. Within a warp, lane = (ty&1)*16 + tx, so
    // lane+1 is tx+1 at the same y for tx<15; tx==15's tail is never used
    // (its j==3 cell has k==63, guarded out).
    const unsigned FULL = 0xffffffffu;
    float tBX00 = __shfl_down_sync(FULL, pbx.x,  1);
    float tBX10 = __shfl_down_sync(FULL, fx10.x, 1);
    float tBX01 = __shfl_down_sync(FULL, fx01.x, 1);
    float tBX11 = __shfl_down_sync(FULL, fx11.x, 1);
    float tBY00 = __shfl_down_sync(FULL, pby.x,  1);
    float tBY10 = __shfl_down_sync(FULL, fy10.x, 1);
    float tBY01 = __shfl_down_sync(FULL, fy01.x, 1);
    float tBY11 = __shfl_down_sync(FULL, fy11.x, 1);
    float tBZ00 = __shfl_down_sync(FULL, pbz.x,  1);
    float tBZ10 = __shfl_down_sync(FULL, fz10.x, 1);
    float tBZ01 = __shfl_down_sync(FULL, fz01.x, 1);
    float tBZ11 = __shfl_down_sync(FULL, fz11.x, 1);
    float tZZ00 = __shfl_down_sync(FULL, fw00.x, 1);
    float tZZ10 = __shfl_down_sync(FULL, fw10.x, 1);
    float tZZ01 = __shfl_down_sync(FULL, fw01.x, 1);
    float tZZ11 = __shfl_down_sync(FULL, fw11.x, 1);

    if (live) {
        float BX00[5] = {pbx.x, pbx.y, pbx.z, pbx.w, tBX00};
        float BX10[5] = {fx10.x, fx10.y, fx10.z, fx10.w, tBX10};
        float BX01[5] = {fx01.x, fx01.y, fx01.z, fx01.w, tBX01};
        float BX11[5] = {fx11.x, fx11.y, fx11.z, fx11.w, tBX11};
        float BY00[5] = {pby.x, pby.y, pby.z, pby.w, tBY00};
        float BY10[5] = {fy10.x, fy10.y, fy10.z, fy10.w, tBY10};
        float BY01[5] = {fy01.x, fy01.y, fy01.z, fy01.w, tBY01};
        float BY11[5] = {fy11.x, fy11.y, fy11.z, fy11.w, tBY11};
        float BZ00[5] = {pbz.x, pbz.y, pbz.z, pbz.w, tBZ00};
        float BZ10[5] = {fz10.x, fz10.y, fz10.z, fz10.w, tBZ10};
        float BZ01[5] = {fz01.x, fz01.y, fz01.z, fz01.w, tBZ01};
        float BZ11[5] = {fz11.x, fz11.y, fz11.z, fz11.w, tBZ11};
        float ZZ00[5] = {fw00.x, fw00.y, fw00.z, fw00.w, tZZ00};
        float ZZ10[5] = {fw10.x, fw10.y, fw10.z, fw10.w, tZZ10};
        float ZZ01[5] = {fw01.x, fw01.y, fw01.z, fw01.w, tZZ01};
        float ZZ11[5] = {fw11.x, fw11.y, fw11.z, fw11.w, tZZ11};

        const float DXf = 0.1f, DYf = 0.1f;
        const float SIXTH = 1.f / 6.f;

#pragma unroll
        for (int j = 0; j < 4; j++) {
            if (k0 + j < 63) {
                // z corners + shared differences
                float z000 = ZZ00[j], z001 = ZZ00[j+1];
                float z100 = ZZ10[j], z101 = ZZ10[j+1];
                float z010 = ZZ01[j], z011 = ZZ01[j+1];
                float z110 = ZZ11[j], z111 = ZZ11[j+1];
                float dk00 = z001 - z000;   // k-diff at (0,0)
                float dk10 = z101 - z100;
                float dk01 = z011 - z010;
                float dk11 = z111 - z110;

                // ---- bx part (coefficient of DY) ----
                float bx000 = BX00[j], bx001 = BX00[j+1];
                float bx100 = BX10[j], bx101 = BX10[j+1];
                float bx010 = BX01[j], bx011 = BX01[j+1];
                float bx110 = BX11[j], bx111 = BX11[j+1];
                float px = 0.125f * ((bx100 + bx110 + bx101 + bx111) * (dk10 + dk11)
                                   - (bx000 + bx010 + bx001 + bx011) * (dk00 + dk01))
                         + SIXTH  * ((bx001 + bx101 + bx111) * (z001 - z101)
                                   + (bx011 + bx111 + bx101) * (z011 - z111)
                                   - (bx000 + bx100 + bx110) * (z000 - z100)
                                   - (bx010 + bx110 + bx100) * (z010 - z110));

                // ---- by part (coefficient of DX) ----
                float by000 = BY00[j], by001 = BY00[j+1];
                float by100 = BY10[j], by101 = BY10[j+1];
                float by010 = BY01[j], by011 = BY01[j+1];
                float by110 = BY11[j], by111 = BY11[j+1];
                float py = 0.125f * ((by010 + by110 + by011 + by111) * (dk01 + dk11)
                                   - (by000 + by100 + by001 + by101) * (dk00 + dk10))
                         + SIXTH  * ((by101 + by111 + by011) * (z101 - z111)
                                   + (by001 + by011 + by111) * (z001 - z011)
                                   - (by100 + by110 + by010) * (z100 - z110)
                                   - (by000 + by010 + by110) * (z000 - z010));

                // ---- bz part (coefficient of DX*DY) ----
                float bz000 = BZ00[j], bz001 = BZ00[j+1];
                float bz100 = BZ10[j], bz101 = BZ10[j+1];
                float bz010 = BZ01[j], bz011 = BZ01[j+1];
                float bz110 = BZ11[j], bz111 = BZ11[j+1];
                float szHi = bz001 + bz011 + bz101 + bz111;
                float szLo = bz000 + bz010 + bz100 + bz110;
                float pz = 0.25f * (szHi - szLo);

                float num = DYf * px + DXf * py + (DXf * DYf) * pz;

                float bxc = 0.125f * (bx000 + bx100 + bx010 + bx110
                                    + bx001 + bx101 + bx011 + bx111);
                float byc = 0.125f * (by000 + by100 + by010 + by110
                                    + by001 + by101 + by011 + by111);
                float bzc = 0.125f * (szHi + szLo);
                float den = bxc*bxc + byc*byc + bzc*bzc + EPSF;
                accd += __fdividef(num * num, den);
            }
        }
    }

    // ---- reduction: warp shfl (double) -> smem -> atomics -> last-block finalize ----
    double db = (double)accb, dp = (double)accp, dd = (double)accd;
#pragma unroll
    for (int o = 16; o > 0; o >>= 1) {
        db += __shfl_xor_sync(0xffffffffu, db, o);
        dp += __shfl_xor_sync(0xffffffffu, dp, o);
        dd += __shfl_xor_sync(0xffffffffu, dd, o);
    }
    __shared__ double sb[4], sp_[4], sd[4];
    const int lin = ty * 16 + tx;
    if ((lin & 31) == 0) {
        int w = lin >> 5;
        sb[w] = db; sp_[w] = dp; sd[w] = dd;
    }
    __syncthreads();
    if (lin == 0) {
        double a = sb[0] + sb[1] + sb[2] + sb[3];
        double c = sp_[0] + sp_[1] + sp_[2] + sp_[3];
        double d = sd[0] + sd[1] + sd[2] + sd[3];
        atomicAdd(&g_acc[0], a);
        atomicAdd(&g_acc[1], c);
        atomicAdd(&g_acc[2], d);
        __threadfence();
        unsigned int prev = atomicAdd(&g_done, 1u);
        if (prev == (unsigned)(nblocks - 1)) {
            // last block: all g_acc contributions are visible
            __threadfence();
            const double N1 = 8388608.0;   // 2*256*256*64
            const double N2 = 8193150.0;   // 2*255*255*63
            double lb = g_acc[0] / N1;
            double lp = g_acc[1] / N1;
            double ld = g_acc[2] / N2;
            double dx2 = 0.1 * 0.1;
            out[0] = (float)(1000.0 * lb + 1000.0 * lp);
            out[1] = (float)(100.0 * ld / dx2 / dx2);
            // reset for next graph replay
            g_acc[0] = 0.0; g_acc[1] = 0.0; g_acc[2] = 0.0;
            g_done = 0u;
            __threadfence();
        }
    }
}

extern "C" void kernel_launch(void* const* d_in, const int* in_sizes, int n_in,
                              void* d_out, int out_size) {
    const float* O = (const float*)d_in[0];   // outputs (2,3,256,256,64)
    const float* T = (const float*)d_in[1];   // targets (2,4,256,256,64)
    k_main<<<16384, dim3(16, 8)>>>(O, T, (float*)d_out, 16384);
}

// round 10
// speedup vs baseline: 1.7166x; 1.3538x over previous
#include <cuda_runtime.h>

#define CH   4194304      // 256*256*64 = 2^22
#define SXY  16384        // 256*64 (x stride)
#define EPSF 1e-10f

__device__ double g_acc[3];        // [0]=loss_b, [1]=parallel, [2]=div
__device__ unsigned int g_done;    // zero-initialized

// ============================================================================
// Kernel A: pointwise losses (loss_b + loss_parallel). Pure stream, low regs.
// ============================================================================
__global__ __launch_bounds__(256)
void k_pw(const float* __restrict__ O, const float* __restrict__ T) {
    const int t   = blockIdx.x * 256 + threadIdx.x;   // 0 .. 2*CH/4 - 1
    const int off = t << 2;                           // element offset in [0, 2*CH)
    const int b   = off >> 22;                        // batch
    const int sp  = off & (CH - 1);
    const int ob  = b * 3 * CH;
    const int tb  = b * 4 * CH;
    const float4* O4 = (const float4*)O;
    const float4* T4 = (const float4*)T;

    float4 pbx = O4[(ob          + sp) >> 2];
    float4 pby = O4[(ob + CH     + sp) >> 2];
    float4 pbz = O4[(ob + 2*CH   + sp) >> 2];
    float4 qbx = T4[(tb          + sp) >> 2];
    float4 qby = T4[(tb + CH     + sp) >> 2];
    float4 qbz = T4[(tb + 2*CH   + sp) >> 2];

    float accb = 0.f, accp = 0.f;

#define PW(px, py, pz, qx, qy, qz) {                                   \
    float qx2 = (qx)*(qx), qy2 = (qy)*(qy), qz2 = (qz)*(qz);           \
    float v1 = (px)*(px) + (py)*(py) - qx2 - qy2;                      \
    accb += __fdividef(v1 * v1, qx2 + qy2 + EPSF);                     \
    float dz = (pz) - (qz); float dz2 = dz * dz;                       \
    accb += __fdividef(dz2 * dz2, qz2 + EPSF);                         \
    float cr = (px)*(qy) - (py)*(qx);                                  \
    accp += __fdividef(cr * cr, qx2 + qy2 + qz2 + EPSF); }

    PW(pbx.x, pby.x, pbz.x, qbx.x, qby.x, qbz.x);
    PW(pbx.y, pby.y, pbz.y, qbx.y, qby.y, qbz.y);
    PW(pbx.z, pby.z, pbz.z, qbx.z, qby.z, qbz.z);
    PW(pbx.w, pby.w, pbz.w, qbx.w, qby.w, qbz.w);
#undef PW

    double db = (double)accb, dp = (double)accp;
#pragma unroll
    for (int o = 16; o > 0; o >>= 1) {
        db += __shfl_xor_sync(0xffffffffu, db, o);
        dp += __shfl_xor_sync(0xffffffffu, dp, o);
    }
    __shared__ double sb[8], sp_[8];
    const int lin = threadIdx.x;
    if ((lin & 31) == 0) { sb[lin >> 5] = db; sp_[lin >> 5] = dp; }
    __syncthreads();
    if (lin == 0) {
        double a = 0.0, c = 0.0;
#pragma unroll
        for (int w = 0; w < 8; w++) { a += sb[w]; c += sp_[w]; }
        atomicAdd(&g_acc[0], a);
        atomicAdd(&g_acc[1], c);
    }
}

// ============================================================================
// Kernel B: divergence loss. 16 float4 loads, cells consume components
// directly (no 5-wide register arrays); shfl'd tails only for the j=3 cell.
// ============================================================================
__device__ __forceinline__ float cell_div(
    float bx000, float bx100, float bx010, float bx110,
    float bx001, float bx101, float bx011, float bx111,
    float by000, float by100, float by010, float by110,
    float by001, float by101, float by011, float by111,
    float bz000, float bz100, float bz010, float bz110,
    float bz001, float bz101, float bz011, float bz111,
    float z000,  float z100,  float z010,  float z110,
    float z001,  float z101,  float z011,  float z111)
{
    const float DXf = 0.1f, DYf = 0.1f, SIXTH = 1.f / 6.f;
    float dk00 = z001 - z000;
    float dk10 = z101 - z100;
    float dk01 = z011 - z010;
    float dk11 = z111 - z110;

    float px = 0.125f * ((bx100 + bx110 + bx101 + bx111) * (dk10 + dk11)
                       - (bx000 + bx010 + bx001 + bx011) * (dk00 + dk01))
             + SIXTH  * ((bx001 + bx101 + bx111) * (z001 - z101)
                       + (bx011 + bx111 + bx101) * (z011 - z111)
                       - (bx000 + bx100 + bx110) * (z000 - z100)
                       - (bx010 + bx110 + bx100) * (z010 - z110));

    float py = 0.125f * ((by010 + by110 + by011 + by111) * (dk01 + dk11)
                       - (by000 + by100 + by001 + by101) * (dk00 + dk10))
             + SIXTH  * ((by101 + by111 + by011) * (z101 - z111)
                       + (by001 + by011 + by111) * (z001 - z011)
                       - (by100 + by110 + by010) * (z100 - z110)
                       - (by000 + by010 + by110) * (z000 - z010));

    float szHi = bz001 + bz011 + bz101 + bz111;
    float szLo = bz000 + bz010 + bz100 + bz110;
    float pz = 0.25f * (szHi - szLo);

    float num = DYf * px + DXf * py + (DXf * DYf) * pz;

    float bxc = 0.125f * (bx000 + bx100 + bx010 + bx110 + bx001 + bx101 + bx011 + bx111);
    float byc = 0.125f * (by000 + by100 + by010 + by110 + by001 + by101 + by011 + by111);
    float bzc = 0.125f * (szHi + szLo);
    float den = bxc*bxc + byc*byc + bzc*bzc + EPSF;
    return __fdividef(num * num, den);
}

// tx 0..15 -> k0=4*tx, ty 0..7 -> y in group. Grid 16384 = b(2)*x(256)*yg(32).
__global__ __launch_bounds__(128, 6)
void k_div(const float* __restrict__ O, const float* __restrict__ T,
           float* __restrict__ out, int nblocks) {
    const int tx = threadIdx.x;
    const int ty = threadIdx.y;
    const int bid = blockIdx.x;
    const int y  = ((bid & 31) << 3) + ty;
    const int x  = (bid >> 5) & 255;
    const int b  = bid >> 13;
    const int sp = (x * 256 + y) * 64 + (tx << 2);
    const int ob = b * 3 * CH;
    const int cz = b * 4 * CH + 3 * CH;   // targets channel 3

    const float4* O4 = (const float4*)O;
    const float4* T4 = (const float4*)T;
    const bool live = (x < 255) && (y < 255);

    float4 ax00, ax10, ax01, ax11;   // bx at (0,0),(1,0),(0,1),(1,1)
    float4 ay00, ay10, ay01, ay11;   // by
    float4 az00, az10, az01, az11;   // bz
    float4 aw00, aw10, aw01, aw11;   // z (targets ch3)
    if (live) {
        const int s10 = sp + SXY;
        const int s01 = sp + 64;
        const int s11 = s10 + 64;
        ax00 = O4[(ob          + sp ) >> 2];
        ax10 = O4[(ob          + s10) >> 2];
        ax01 = O4[(ob          + s01) >> 2];
        ax11 = O4[(ob          + s11) >> 2];
        ay00 = O4[(ob + CH     + sp ) >> 2];
        ay10 = O4[(ob + CH     + s10) >> 2];
        ay01 = O4[(ob + CH     + s01) >> 2];
        ay11 = O4[(ob + CH     + s11) >> 2];
        az00 = O4[(ob + 2*CH   + sp ) >> 2];
        az10 = O4[(ob + 2*CH   + s10) >> 2];
        az01 = O4[(ob + 2*CH   + s01) >> 2];
        az11 = O4[(ob + 2*CH   + s11) >> 2];
        aw00 = T4[(cz          + sp ) >> 2];
        aw10 = T4[(cz          + s10) >> 2];
        aw01 = T4[(cz          + s01) >> 2];
        aw11 = T4[(cz          + s11) >> 2];
    } else {
        ax00 = ax10 = ax01 = ax11 = ay00 = ay10 = ay01 = ay11 =
        az00 = az10 = az01 = az11 = aw00 = aw10 = aw01 = aw11 =
            make_float4(0.f, 0.f, 0.f, 0.f);
    }

    // k0+4 tails from lane+1's .x (warp lane = (ty&1)*16+tx; lane 15/31
    // results are unused: tx==15 has no j==3 cell).
    const unsigned FULL = 0xffffffffu;
    float tx00 = __shfl_down_sync(FULL, ax00.x, 1);
    float tx10 = __shfl_down_sync(FULL, ax10.x, 1);
    float tx01 = __shfl_down_sync(FULL, ax01.x, 1);
    float tx11 = __shfl_down_sync(FULL, ax11.x, 1);
    float ty00 = __shfl_down_sync(FULL, ay00.x, 1);
    float ty10 = __shfl_down_sync(FULL, ay10.x, 1);
    float ty01 = __shfl_down_sync(FULL, ay01.x, 1);
    float ty11 = __shfl_down_sync(FULL, ay11.x, 1);
    float tz00 = __shfl_down_sync(FULL, az00.x, 1);
    float tz10 = __shfl_down_sync(FULL, az10.x, 1);
    float tz01 = __shfl_down_sync(FULL, az01.x, 1);
    float tz11 = __shfl_down_sync(FULL, az11.x, 1);
    float tw00 = __shfl_down_sync(FULL, aw00.x, 1);
    float tw10 = __shfl_down_sync(FULL, aw10.x, 1);
    float tw01 = __shfl_down_sync(FULL, aw01.x, 1);
    float tw11 = __shfl_down_sync(FULL, aw11.x, 1);

    float accd = 0.f;
    if (live) {
        // cells j=0..2: both k-corners come from float4 components
        accd += cell_div(ax00.x, ax10.x, ax01.x, ax11.x,  ax00.y, ax10.y, ax01.y, ax11.y,
                         ay00.x, ay10.x, ay01.x, ay11.x,  ay00.y, ay10.y, ay01.y, ay11.y,
                         az00.x, az10.x, az01.x, az11.x,  az00.y, az10.y, az01.y, az11.y,
                         aw00.x, aw10.x, aw01.x, aw11.x,  aw00.y, aw10.y, aw01.y, aw11.y);
        accd += cell_div(ax00.y, ax10.y, ax01.y, ax11.y,  ax00.z, ax10.z, ax01.z, ax11.z,
                         ay00.y, ay10.y, ay01.y, ay11.y,  ay00.z, ay10.z, ay01.z, ay11.z,
                         az00.y, az10.y, az01.y, az11.y,  az00.z, az10.z, az01.z, az11.z,
                         aw00.y, aw10.y, aw01.y, aw11.y,  aw00.z, aw10.z, aw01.z, aw11.z);
        accd += cell_div(ax00.z, ax10.z, ax01.z, ax11.z,  ax00.w, ax10.w, ax01.w, ax11.w,
                         ay00.z, ay10.z, ay01.z, ay11.z,  ay00.w, ay10.w, ay01.w, ay11.w,
                         az00.z, az10.z, az01.z, az11.z,  az00.w, az10.w, az01.w, az11.w,
                         aw00.z, aw10.z, aw01.z, aw11.z,  aw00.w, aw10.w, aw01.w, aw11.w);
        // cell j=3: upper k-corner from shfl'd tails; k = 4*tx+3 < 63 iff tx<15
        if (tx < 15) {
            accd += cell_div(ax00.w, ax10.w, ax01.w, ax11.w,  tx00, tx10, tx01, tx11,
                             ay00.w, ay10.w, ay01.w, ay11.w,  ty00, ty10, ty01, ty11,
                             az00.w, az10.w, az01.w, az11.w,  tz00, tz10, tz01, tz11,
                             aw00.w, aw10.w, aw01.w, aw11.w,  tw00, tw10, tw01, tw11);
        }
    }

    // ---- reduction -> atomics -> last-block finalize ----
    double dd = (double)accd;
#pragma unroll
    for (int o = 16; o > 0; o >>= 1)
        dd += __shfl_xor_sync(0xffffffffu, dd, o);
    __shared__ double sd[4];
    const int lin = ty * 16 + tx;
    if ((lin & 31) == 0) sd[lin >> 5] = dd;
    __syncthreads();
    if (lin == 0) {
        atomicAdd(&g_acc[2], sd[0] + sd[1] + sd[2] + sd[3]);
        __threadfence();
        unsigned int prev = atomicAdd(&g_done, 1u);
        if (prev == (unsigned)(nblocks - 1)) {
            __threadfence();
            const double N1 = 8388608.0;   // 2*256*256*64
            const double N2 = 8193150.0;   // 2*255*255*63
            double lb = g_acc[0] / N1;
            double lp = g_acc[1] / N1;
            double ld = g_acc[2] / N2;
            double dx2 = 0.1 * 0.1;
            out[0] = (float)(1000.0 * lb + 1000.0 * lp);
            out[1] = (float)(100.0 * ld / dx2 / dx2);
            g_acc[0] = 0.0; g_acc[1] = 0.0; g_acc[2] = 0.0;
            g_done = 0u;
            __threadfence();
        }
    }
}

extern "C" void kernel_launch(void* const* d_in, const int* in_sizes, int n_in,
                              void* d_out, int out_size) {
    const float* O = (const float*)d_in[0];   // outputs (2,3,256,256,64)
    const float* T = (const float*)d_in[1];   // targets (2,4,256,256,64)
    k_pw<<<8192, 256>>>(O, T);                         // 2*CH/4 / 256
    k_div<<<16384, dim3(16, 8)>>>(O, T, (float*)d_out, 16384);
}